// round 6
// baseline (speedup 1.0000x reference)
#include <cuda_runtime.h>
#include <cstdint>

// ============================================================================
// 3-layer MLP via mma.sync.m16n8k8.tf32 on sm_103a (tcgen05 unavailable:
// harness compiles through compute_103 non-'a' virtual arch).
//   out = relu(relu(x@w1+b1)@w2+b2)@w3+b3
// CTA tile 128x256, 512 threads, 4x4 warp grid, warp tile 32x64, BK=16,
// 4-stage cp.async ring. Operands stored K-permuted within 8-col groups
// ([0,4,1,5,2,6,3,7]) so every mma fragment load is a conflict-free lds.64
// (smem rows padded to 24 floats: row bases mod 32 tile all banks).
// All operands pre-rounded to tf32 with cvt.rna (kills truncation bias).
// ============================================================================

#define DINL __device__ __forceinline__

constexpr int BATCH = 4096, IN = 2048, HID = 4096, NCLS = 1000, NCLS_PAD = 1024;

constexpr int BM = 128, BN = 256, BK = 16;
constexpr int STAGES = 4;
constexpr int LDSW = 24;                    // smem row stride (floats)
constexpr int A_STAGE = BM * LDSW * 4;      // 12288 B
constexpr int B_STAGE = BN * LDSW * 4;      // 24576 B
constexpr int B_OFF = STAGES * A_STAGE;
constexpr int SMEM_TOT = STAGES * (A_STAGE + B_STAGE);   // 147456 B

constexpr int MF = 2, NF = 8;               // warp tile 32 x 64

// device scratch (allocation-guard-safe)
__device__ float g_h1 [(size_t)BATCH * HID];
__device__ float g_h2 [(size_t)BATCH * HID];
__device__ float g_xr [(size_t)BATCH * IN];
__device__ float g_w1t[(size_t)HID * IN];
__device__ float g_w2t[(size_t)HID * HID];
__device__ float g_w3t[(size_t)NCLS_PAD * HID];

// ---------------------------------------------------------------- helpers
DINL uint32_t s2u(const void* p) {
    uint32_t a;
    asm("{ .reg .u64 t; cvta.to.shared.u64 t, %1; cvt.u32.u64 %0, t; }"
        : "=r"(a) : "l"(p));
    return a;
}
DINL void cp_async16(uint32_t s, const void* g) {
    asm volatile("cp.async.cg.shared.global [%0], [%1], 16;" :: "r"(s), "l"(g));
}
DINL void cp_commit() { asm volatile("cp.async.commit_group;" ::: "memory"); }
#define CP_WAIT(n) asm volatile("cp.async.wait_group %0;" :: "n"(n) : "memory")

DINL uint2 lds64(uint32_t a) {
    uint2 v;
    asm volatile("ld.shared.v2.b32 {%0,%1}, [%2];" : "=r"(v.x), "=r"(v.y) : "r"(a));
    return v;
}
DINL float rna_tf32(float x) {
    uint32_t o;
    asm("cvt.rna.tf32.f32 %0, %1;" : "=r"(o) : "f"(x));
    return __uint_as_float(o);
}
DINL void mma1688(float* d, const uint32_t* a, const uint32_t* b) {
    asm volatile(
        "mma.sync.aligned.m16n8k8.row.col.f32.tf32.tf32.f32 "
        "{%0,%1,%2,%3}, {%4,%5,%6,%7}, {%8,%9}, {%0,%1,%2,%3};"
        : "+f"(d[0]), "+f"(d[1]), "+f"(d[2]), "+f"(d[3])
        : "r"(a[0]), "r"(a[1]), "r"(a[2]), "r"(a[3]), "r"(b[0]), "r"(b[1]));
}
// within-8 permutation: logical j stored at physical 2*(j&3) + (j>>2)
DINL int kperm(int j) { return 2 * (j & 3) + (j >> 2); }

// ------------------------------------------------------------------ GEMM
// A [M,K] row-major (tf32-rounded, K-permuted), Bt [Npad,K] same layout,
// C [M,N].  flags: bit0 relu, bit1 rna output, bit2 permute output columns.
__global__ __launch_bounds__(512, 1)
void mlp_gemm_mma(const float* __restrict__ A, const float* __restrict__ Bt,
                  const float* __restrict__ bias, float* __restrict__ C,
                  int K, int N, int flags) {
    extern __shared__ char smem[];
    const uint32_t sb = s2u(smem);
    const int tid = threadIdx.x;
    const int wid = tid >> 5, lid = tid & 31;
    const int warp_m = wid & 3;           // 0..3 (M)
    const int warp_n = wid >> 2;          // 0..3 (N)
    const int m0 = blockIdx.x * BM;
    const int n0 = blockIdx.y * BN;
    const int lg = lid >> 2;              // 0..7
    const int lc = lid & 3;               // 0..3

    const float* Ag = A + (size_t)m0 * K;
    const float* Bg = Bt + (size_t)n0 * K;

    auto load_stage = [&](int buf, int kt) {
        const uint32_t abase = sb + buf * A_STAGE;
        const float* ap = Ag + kt * BK;
        {   // 512 chunks of 16B, one per thread
            int row = tid >> 2, j = tid & 3;
            cp_async16(abase + (row * LDSW + j * 4) * 4,
                       ap + (size_t)row * K + j * 4);
        }
        const uint32_t bbase = sb + B_OFF + buf * B_STAGE;
        const float* bp = Bg + kt * BK;
#pragma unroll
        for (int t = 0; t < 2; t++) {     // 1024 chunks
            int ch = tid + t * 512;
            int row = ch >> 2, j = ch & 3;
            cp_async16(bbase + (row * LDSW + j * 4) * 4,
                       bp + (size_t)row * K + j * 4);
        }
    };

    const int ktiles = K / BK;
    for (int s = 0; s < STAGES - 1; s++) { load_stage(s, s); cp_commit(); }

    float acc[MF][NF][4];
#pragma unroll
    for (int i = 0; i < MF; i++)
#pragma unroll
        for (int j = 0; j < NF; j++)
#pragma unroll
            for (int r = 0; r < 4; r++) acc[i][j][r] = 0.f;

    // fragment base addrs (buffer 0): physical 2*lc holds logical cols lc,lc+4
    const uint32_t a_t0 = sb + ((warp_m * 32 + lg) * LDSW + 2 * lc) * 4;
    const uint32_t b_t0 = sb + B_OFF + ((warp_n * 64 + lg) * LDSW + 2 * lc) * 4;

    for (int kt = 0; kt < ktiles; kt++) {
        const int b = kt & (STAGES - 1);
        CP_WAIT(STAGES - 2);
        __syncthreads();

        const int nk = kt + STAGES - 1;
        if (nk < ktiles) load_stage(nk & (STAGES - 1), nk);
        cp_commit();

        const uint32_t ab = a_t0 + b * A_STAGE;
        const uint32_t bb = b_t0 + b * B_STAGE;
#pragma unroll
        for (int kk = 0; kk < 2; kk++) {
            uint32_t af[MF][4];
#pragma unroll
            for (int mf = 0; mf < MF; mf++) {
                uint2 lo = lds64(ab + (mf * 16 * LDSW + kk * 8) * 4);
                uint2 hi = lds64(ab + (mf * 16 * LDSW + 8 * LDSW + kk * 8) * 4);
                af[mf][0] = lo.x; af[mf][1] = hi.x;   // (a0,a2),(a1,a3)
                af[mf][2] = lo.y; af[mf][3] = hi.y;
            }
            uint32_t bf[NF][2];
#pragma unroll
            for (int nf = 0; nf < NF; nf++) {
                uint2 v = lds64(bb + (nf * 8 * LDSW + kk * 8) * 4);
                bf[nf][0] = v.x; bf[nf][1] = v.y;
            }
#pragma unroll
            for (int mf = 0; mf < MF; mf++)
#pragma unroll
                for (int nf = 0; nf < NF; nf++)
                    mma1688(acc[mf][nf], af[mf], bf[nf]);
        }
    }

    // ---- epilogue
    const int do_relu = flags & 1, do_rna = flags & 2, do_perm = flags & 4;
    float bv[NF][2];
#pragma unroll
    for (int nf = 0; nf < NF; nf++) {
        const int c = n0 + warp_n * 64 + nf * 8 + 2 * lc;     // logical col
        bv[nf][0] = (c < N) ? __ldg(bias + c) : 0.f;
        bv[nf][1] = (c + 1 < N) ? __ldg(bias + c + 1) : 0.f;
    }
    const int poff = 4 * (lc & 1) + (lc >> 1);   // physical slot of logical 2lc
#pragma unroll
    for (int mf = 0; mf < MF; mf++) {
#pragma unroll
        for (int r2 = 0; r2 < 2; r2++) {
            const int m = m0 + warp_m * 32 + mf * 16 + lg + r2 * 8;
            float* crow = C + (size_t)m * N;
#pragma unroll
            for (int nf = 0; nf < NF; nf++) {
                const int c = n0 + warp_n * 64 + nf * 8 + 2 * lc;
                float v0 = acc[mf][nf][r2 * 2 + 0] + bv[nf][0];
                float v1 = acc[mf][nf][r2 * 2 + 1] + bv[nf][1];
                if (do_relu) { v0 = fmaxf(v0, 0.f); v1 = fmaxf(v1, 0.f); }
                if (do_rna)  { v0 = rna_tf32(v0);  v1 = rna_tf32(v1); }
                if (do_perm) {
                    const int cg = c - 2 * lc;     // 8-group base
                    crow[cg + poff]     = v0;      // logical 2lc
                    crow[cg + poff + 2] = v1;      // logical 2lc+1
                } else if (c < N) {
                    *(float2*)(crow + c) = make_float2(v0, v1);
                }
            }
        }
    }
}

// ---------------------------------------------------- fused prep (1 launch)
// jobs: 3 weight transposes (+rna, +K-perm) and x round/permute.
__device__ void transpose_job(const float* __restrict__ s, float* __restrict__ d,
                              int R, int C, int bx, int by) {
    __shared__ float t[32][33];
    const int tid = threadIdx.x;
    const int x = tid & 31, y = tid >> 5;   // 32 x 8
    const int c0 = bx * 32, r0 = by * 32;
#pragma unroll
    for (int i = y; i < 32; i += 8) {
        int r = r0 + i, c = c0 + x;
        t[i][x] = (c < C) ? s[(size_t)r * C + c] : 0.f;
    }
    __syncthreads();
#pragma unroll
    for (int i = y; i < 32; i += 8) {
        int cc = c0 + i, rr = r0 + x;
        int rp = (rr & ~7) | kperm(rr & 7);
        d[(size_t)cc * R + rp] = rna_tf32(t[x][i]);
    }
}

constexpr int G_W1 = (HID / 32) * (IN / 32);        // 8192
constexpr int G_W2 = (HID / 32) * (HID / 32);       // 16384
constexpr int G_W3 = (NCLS_PAD / 32) * (HID / 32);  // 4096
constexpr int G_X  = (BATCH * IN) / 2048;           // 4096
constexpr int G_PREP = G_W1 + G_W2 + G_W3 + G_X;    // 32768

__global__ __launch_bounds__(256)
void prep_all(const float* __restrict__ w1, const float* __restrict__ w2,
              const float* __restrict__ w3, const float* __restrict__ x,
              float* __restrict__ w1t, float* __restrict__ w2t,
              float* __restrict__ w3t, float* __restrict__ xr) {
    int id = blockIdx.x;
    if (id < G_W1) {
        transpose_job(w1, w1t, IN, HID, id % (HID / 32), id / (HID / 32));
        return;
    }
    id -= G_W1;
    if (id < G_W2) {
        transpose_job(w2, w2t, HID, HID, id % (HID / 32), id / (HID / 32));
        return;
    }
    id -= G_W2;
    if (id < G_W3) {
        transpose_job(w3, w3t, HID, NCLS, id % (NCLS_PAD / 32), id / (NCLS_PAD / 32));
        return;
    }
    id -= G_W3;
    // x: round + K-permute, 8 floats/thread
    const size_t base = (size_t)id * 2048 + threadIdx.x * 8;
    float4 a = *(const float4*)(x + base);
    float4 b = *(const float4*)(x + base + 4);
    float4 o0 = make_float4(rna_tf32(a.x), rna_tf32(b.x), rna_tf32(a.y), rna_tf32(b.y));
    float4 o1 = make_float4(rna_tf32(a.z), rna_tf32(b.z), rna_tf32(a.w), rna_tf32(b.w));
    *(float4*)(xr + base)     = o0;
    *(float4*)(xr + base + 4) = o1;
}

// ----------------------------------------------------------------- launcher
extern "C" void kernel_launch(void* const* d_in, const int* in_sizes, int n_in,
                              void* d_out, int out_size) {
    (void)in_sizes; (void)n_in; (void)out_size;
    const float* x  = (const float*)d_in[0];
    const float* w1 = (const float*)d_in[1];
    const float* b1 = (const float*)d_in[2];
    const float* w2 = (const float*)d_in[3];
    const float* b2 = (const float*)d_in[4];
    const float* w3 = (const float*)d_in[5];
    const float* b3 = (const float*)d_in[6];
    float* out = (float*)d_out;

    float *h1, *h2, *xr, *w1t, *w2t, *w3t;
    cudaGetSymbolAddress((void**)&h1,  g_h1);
    cudaGetSymbolAddress((void**)&h2,  g_h2);
    cudaGetSymbolAddress((void**)&xr,  g_xr);
    cudaGetSymbolAddress((void**)&w1t, g_w1t);
    cudaGetSymbolAddress((void**)&w2t, g_w2t);
    cudaGetSymbolAddress((void**)&w3t, g_w3t);

    cudaFuncSetAttribute(mlp_gemm_mma,
                         cudaFuncAttributeMaxDynamicSharedMemorySize, SMEM_TOT);

    prep_all<<<G_PREP, 256>>>(w1, w2, w3, x, w1t, w2t, w3t, xr);

    // grid.x = M tiles: a wave's CTAs share weight tiles via L2
    mlp_gemm_mma<<<dim3(BATCH / BM, HID / BN), 512, SMEM_TOT>>>(
        xr, w1t, b1, h1, IN, HID, /*relu|rna|perm*/ 7);
    mlp_gemm_mma<<<dim3(BATCH / BM, HID / BN), 512, SMEM_TOT>>>(
        h1, w2t, b2, h2, HID, HID, 7);
    mlp_gemm_mma<<<dim3(BATCH / BM, NCLS_PAD / BN), 512, SMEM_TOT>>>(
        h2, w3t, b3, out, HID, NCLS, 0);
}

// round 7
// speedup vs baseline: 1.5963x; 1.5963x over previous
#include <cuda_runtime.h>
#include <cstdint>

// ============================================================================
// 3-layer MLP via mma.sync.m16n8k8.tf32 on sm_103a (tcgen05 rejected by the
// harness's compute_103 virtual arch).
//   out = relu(relu(x@w1+b1)@w2+b2)@w3+b3
// CTA tile 128x256, 256 threads, 2x4 warp grid, warp tile 64x64 (crossbar-
// balanced), BK=16, 4-stage cp.async ring, persistent CTAs (grid=152).
// Operands stored with full-16 K-permutation (logical k -> phys 4*(k&3)+(k>>2))
// so each fragment row is ONE conflict-free lds.128 covering both k=8 halves.
// Smem row stride 16 floats (64B) -- no padding needed under this scheme.
// All operands pre-rounded to tf32 with cvt.rna (kills truncation bias).
// ============================================================================

#define DINL __device__ __forceinline__

constexpr int BATCH = 4096, IN = 2048, HID = 4096, NCLS = 1000, NCLS_PAD = 1024;

constexpr int BM = 128, BN = 256, BK = 16;
constexpr int STAGES = 4;
constexpr int A_STAGE = BM * BK * 4;        // 8192 B
constexpr int B_STAGE = BN * BK * 4;        // 16384 B
constexpr int B_OFF = STAGES * A_STAGE;     // 32768
constexpr int SMEM_TOT = STAGES * (A_STAGE + B_STAGE);   // 98304 B

constexpr int MF = 4, NF = 8;               // warp tile 64 x 64
constexpr int NSM = 152;                    // GB300

// device scratch (allocation-guard-safe)
__device__ float g_h1 [(size_t)BATCH * HID];
__device__ float g_h2 [(size_t)BATCH * HID];
__device__ float g_xr [(size_t)BATCH * IN];
__device__ float g_w1t[(size_t)HID * IN];
__device__ float g_w2t[(size_t)HID * HID];
__device__ float g_w3t[(size_t)NCLS_PAD * HID];

// ---------------------------------------------------------------- helpers
DINL uint32_t s2u(const void* p) {
    uint32_t a;
    asm("{ .reg .u64 t; cvta.to.shared.u64 t, %1; cvt.u32.u64 %0, t; }"
        : "=r"(a) : "l"(p));
    return a;
}
DINL void cp_async16(uint32_t s, const void* g) {
    asm volatile("cp.async.cg.shared.global [%0], [%1], 16;" :: "r"(s), "l"(g));
}
DINL void cp_commit() { asm volatile("cp.async.commit_group;" ::: "memory"); }
#define CP_WAIT(n) asm volatile("cp.async.wait_group %0;" :: "n"(n) : "memory")

DINL uint4 lds128(uint32_t a) {
    uint4 v;
    asm volatile("ld.shared.v4.b32 {%0,%1,%2,%3}, [%4];"
                 : "=r"(v.x), "=r"(v.y), "=r"(v.z), "=r"(v.w) : "r"(a));
    return v;
}
DINL float rna_tf32(float x) {
    uint32_t o;
    asm("cvt.rna.tf32.f32 %0, %1;" : "=r"(o) : "f"(x));
    return __uint_as_float(o);
}
DINL void mma1688(float* d, uint32_t a0, uint32_t a1, uint32_t a2, uint32_t a3,
                  uint32_t b0, uint32_t b1) {
    asm volatile(
        "mma.sync.aligned.m16n8k8.row.col.f32.tf32.tf32.f32 "
        "{%0,%1,%2,%3}, {%4,%5,%6,%7}, {%8,%9}, {%0,%1,%2,%3};"
        : "+f"(d[0]), "+f"(d[1]), "+f"(d[2]), "+f"(d[3])
        : "r"(a0), "r"(a1), "r"(a2), "r"(a3), "r"(b0), "r"(b1));
}
// full-16 permutation: logical j (0..15) stored at phys 4*(j&3) + (j>>2)
DINL int kperm16(int j) { return 4 * (j & 3) + ((j >> 2) & 3); }

// ------------------------------------------------------------------ GEMM
// A [M,K] row-major (tf32-rounded, 16-permuted), Bt [Npad,K] same layout,
// C [M,N].  flags: bit0 relu, bit1 rna output, bit2 permute output cols.
// Persistent: tiles = Mt*Nt walked M-major with stride gridDim.x.
__global__ __launch_bounds__(256, 1)
void mlp_gemm_mma(const float* __restrict__ A, const float* __restrict__ Bt,
                  const float* __restrict__ bias, float* __restrict__ C,
                  int K, int N, int Mt, int Nt, int flags) {
    extern __shared__ char smem[];
    const uint32_t sb = s2u(smem);
    const int tid = threadIdx.x;
    const int wid = tid >> 5, lid = tid & 31;
    const int warp_m = wid & 1;           // 0..1
    const int warp_n = wid >> 1;          // 0..3
    const int lg = lid >> 2;              // 0..7
    const int lc = lid & 3;               // 0..3
    const int ktiles = K / BK;
    const int ntile = Mt * Nt;
    const int do_relu = flags & 1, do_rna = flags & 2, do_perm = flags & 4;

    // per-thread cp.async targets (row, 16B chunk)
    const int a_row = tid >> 1, a_j = tid & 1;          // 128 rows x 2 halves? no:
    // A: 512 chunks = 128 rows x 4; 2 per thread. B: 1024 chunks; 4 per thread.

    for (int idx = blockIdx.x; idx < ntile; idx += gridDim.x) {
        const int m0 = (idx % Mt) * BM;
        const int n0 = (idx / Mt) * BN;
        const float* Ag = A + (size_t)m0 * K;
        const float* Bg = Bt + (size_t)n0 * K;

        auto load_stage = [&](int buf, int kt) {
            const uint32_t abase = sb + buf * A_STAGE;
            const float* ap = Ag + kt * BK;
#pragma unroll
            for (int t = 0; t < 2; t++) {
                int ch = tid + t * 256;
                int row = ch >> 2, j = ch & 3;
                cp_async16(abase + row * 64 + j * 16,
                           ap + (size_t)row * K + j * 4);
            }
            const uint32_t bbase = sb + B_OFF + buf * B_STAGE;
            const float* bp = Bg + kt * BK;
#pragma unroll
            for (int t = 0; t < 4; t++) {
                int ch = tid + t * 256;
                int row = ch >> 2, j = ch & 3;
                cp_async16(bbase + row * 64 + j * 16,
                           bp + (size_t)row * K + j * 4);
            }
        };

        for (int s = 0; s < STAGES - 1; s++) { load_stage(s, s); cp_commit(); }

        float acc[MF][NF][4];
#pragma unroll
        for (int i = 0; i < MF; i++)
#pragma unroll
            for (int j = 0; j < NF; j++)
#pragma unroll
                for (int r = 0; r < 4; r++) acc[i][j][r] = 0.f;

        // fragment base byte addrs (buffer 0): row*64 + 16*lc
        const uint32_t a_t0 = sb + (warp_m * 64 + lg) * 64 + 16 * lc;
        const uint32_t b_t0 = sb + B_OFF + (warp_n * 64 + lg) * 64 + 16 * lc;

        for (int kt = 0; kt < ktiles; kt++) {
            const int b = kt & (STAGES - 1);
            CP_WAIT(STAGES - 2);
            __syncthreads();

            const int nk = kt + STAGES - 1;
            if (nk < ktiles) load_stage(nk & (STAGES - 1), nk);
            cp_commit();

            const uint32_t ab = a_t0 + b * A_STAGE;
            const uint32_t bb = b_t0 + b * B_STAGE;

            // one lds.128 per fragment row covers BOTH k=8 halves
            uint4 alo[MF], ahi[MF];
#pragma unroll
            for (int mf = 0; mf < MF; mf++) {
                alo[mf] = lds128(ab + mf * 1024);        // rows lg
                ahi[mf] = lds128(ab + mf * 1024 + 512);  // rows lg+8
            }
            uint4 bv[NF];
#pragma unroll
            for (int nf = 0; nf < NF; nf++)
                bv[nf] = lds128(bb + nf * 512);

#pragma unroll
            for (int mf = 0; mf < MF; mf++)
#pragma unroll
                for (int nf = 0; nf < NF; nf++) {
                    mma1688(acc[mf][nf], alo[mf].x, ahi[mf].x, alo[mf].y,
                            ahi[mf].y, bv[nf].x, bv[nf].y);          // kk=0
                    mma1688(acc[mf][nf], alo[mf].z, ahi[mf].z, alo[mf].w,
                            ahi[mf].w, bv[nf].z, bv[nf].w);          // kk=1
                }
        }

        // ---- epilogue (acc in regs; no smem use)
        float bvv[NF][2];
#pragma unroll
        for (int nf = 0; nf < NF; nf++) {
            const int c = n0 + warp_n * 64 + nf * 8 + 2 * lc;
            bvv[nf][0] = (c < N) ? __ldg(bias + c) : 0.f;
            bvv[nf][1] = (c + 1 < N) ? __ldg(bias + c + 1) : 0.f;
        }
#pragma unroll
        for (int mf = 0; mf < MF; mf++) {
#pragma unroll
            for (int r2 = 0; r2 < 2; r2++) {
                const int m = m0 + warp_m * 64 + mf * 16 + lg + r2 * 8;
                float* crow = C + (size_t)m * N;
#pragma unroll
                for (int nf = 0; nf < NF; nf++) {
                    const int c = n0 + warp_n * 64 + nf * 8 + 2 * lc;
                    float v0 = acc[mf][nf][r2 * 2 + 0] + bvv[nf][0];
                    float v1 = acc[mf][nf][r2 * 2 + 1] + bvv[nf][1];
                    if (do_relu) { v0 = fmaxf(v0, 0.f); v1 = fmaxf(v1, 0.f); }
                    if (do_rna)  { v0 = rna_tf32(v0);  v1 = rna_tf32(v1); }
                    if (do_perm) {
                        const int g = c & ~15;
                        crow[g + kperm16(c & 15)]       = v0;
                        crow[g + kperm16((c + 1) & 15)] = v1;
                    } else if (c < N) {
                        *(float2*)(crow + c) = make_float2(v0, v1);
                    }
                }
            }
        }
        // next tile's prologue only writes buffers whose last readers are
        // >= 3 kts old -- already fenced by the per-kt __syncthreads chain.
    }
}

// ---------------------------------------------------- fused prep (1 launch)
__device__ void transpose_job(const float* __restrict__ s, float* __restrict__ d,
                              int R, int C, int bx, int by) {
    __shared__ float t[32][33];
    const int tid = threadIdx.x;
    const int x = tid & 31, y = tid >> 5;   // 32 x 8
    const int c0 = bx * 32, r0 = by * 32;
#pragma unroll
    for (int i = y; i < 32; i += 8) {
        int r = r0 + i, c = c0 + x;
        t[i][x] = (c < C) ? s[(size_t)r * C + c] : 0.f;
    }
    __syncthreads();
#pragma unroll
    for (int i = y; i < 32; i += 8) {
        int cc = c0 + i, rr = r0 + x;
        int rp = (rr & ~15) | kperm16(rr & 15);
        d[(size_t)cc * R + rp] = rna_tf32(t[x][i]);
    }
}

constexpr int G_W1 = (HID / 32) * (IN / 32);        // 8192
constexpr int G_W2 = (HID / 32) * (HID / 32);       // 16384
constexpr int G_W3 = (NCLS_PAD / 32) * (HID / 32);  // 4096
constexpr int G_X  = (BATCH * IN) / 4096;           // 2048
constexpr int G_PREP = G_W1 + G_W2 + G_W3 + G_X;

__global__ __launch_bounds__(256)
void prep_all(const float* __restrict__ w1, const float* __restrict__ w2,
              const float* __restrict__ w3, const float* __restrict__ x,
              float* __restrict__ w1t, float* __restrict__ w2t,
              float* __restrict__ w3t, float* __restrict__ xr) {
    int id = blockIdx.x;
    if (id < G_W1) {
        transpose_job(w1, w1t, IN, HID, id % (HID / 32), id / (HID / 32));
        return;
    }
    id -= G_W1;
    if (id < G_W2) {
        transpose_job(w2, w2t, HID, HID, id % (HID / 32), id / (HID / 32));
        return;
    }
    id -= G_W2;
    if (id < G_W3) {
        transpose_job(w3, w3t, HID, NCLS, id % (NCLS_PAD / 32), id / (NCLS_PAD / 32));
        return;
    }
    id -= G_W3;
    // x: rna + 16-perm. 16 floats/thread; the permutation is a 4x4 transpose
    // of four consecutive float4s.
    const size_t base = (size_t)id * 4096 + threadIdx.x * 16;
    float4 i0 = *(const float4*)(x + base);
    float4 i1 = *(const float4*)(x + base + 4);
    float4 i2 = *(const float4*)(x + base + 8);
    float4 i3 = *(const float4*)(x + base + 12);
    float4 o0 = make_float4(rna_tf32(i0.x), rna_tf32(i1.x), rna_tf32(i2.x), rna_tf32(i3.x));
    float4 o1 = make_float4(rna_tf32(i0.y), rna_tf32(i1.y), rna_tf32(i2.y), rna_tf32(i3.y));
    float4 o2 = make_float4(rna_tf32(i0.z), rna_tf32(i1.z), rna_tf32(i2.z), rna_tf32(i3.z));
    float4 o3 = make_float4(rna_tf32(i0.w), rna_tf32(i1.w), rna_tf32(i2.w), rna_tf32(i3.w));
    *(float4*)(xr + base)      = o0;
    *(float4*)(xr + base + 4)  = o1;
    *(float4*)(xr + base + 8)  = o2;
    *(float4*)(xr + base + 12) = o3;
}

// ----------------------------------------------------------------- launcher
extern "C" void kernel_launch(void* const* d_in, const int* in_sizes, int n_in,
                              void* d_out, int out_size) {
    (void)in_sizes; (void)n_in; (void)out_size;
    const float* x  = (const float*)d_in[0];
    const float* w1 = (const float*)d_in[1];
    const float* b1 = (const float*)d_in[2];
    const float* w2 = (const float*)d_in[3];
    const float* b2 = (const float*)d_in[4];
    const float* w3 = (const float*)d_in[5];
    const float* b3 = (const float*)d_in[6];
    float* out = (float*)d_out;

    float *h1, *h2, *xr, *w1t, *w2t, *w3t;
    cudaGetSymbolAddress((void**)&h1,  g_h1);
    cudaGetSymbolAddress((void**)&h2,  g_h2);
    cudaGetSymbolAddress((void**)&xr,  g_xr);
    cudaGetSymbolAddress((void**)&w1t, g_w1t);
    cudaGetSymbolAddress((void**)&w2t, g_w2t);
    cudaGetSymbolAddress((void**)&w3t, g_w3t);

    cudaFuncSetAttribute(mlp_gemm_mma,
                         cudaFuncAttributeMaxDynamicSharedMemorySize, SMEM_TOT);

    prep_all<<<G_PREP, 256>>>(w1, w2, w3, x, w1t, w2t, w3t, xr);

    const int MT = BATCH / BM;                 // 32
    mlp_gemm_mma<<<NSM, 256, SMEM_TOT>>>(
        xr, w1t, b1, h1, IN, HID, MT, HID / BN, /*relu|rna|perm*/ 7);
    mlp_gemm_mma<<<NSM, 256, SMEM_TOT>>>(
        h1, w2t, b2, h2, HID, HID, MT, HID / BN, 7);
    mlp_gemm_mma<<<128, 256, SMEM_TOT>>>(
        h2, w3t, b3, out, HID, NCLS, MT, NCLS_PAD / BN, 0);
}

// round 8
// speedup vs baseline: 1.8728x; 1.1732x over previous
#include <cuda_runtime.h>
#include <cstdint>

// ============================================================================
// 3-layer MLP via mma.sync.m16n8k8.tf32 on sm_103a (tcgen05 rejected by the
// harness's compute_103 virtual arch).
//   out = relu(relu(x@w1+b1)@w2+b2)@w3+b3
// CTA tile 128x128, 256 threads, 2(M)x4(N) warp grid, warp tile 64x32
// (acc = 64 regs -> 2 CTAs/SM via __launch_bounds__(256,2); 16 warps/SM).
// BK=16, 4-stage cp.async ring, persistent CTAs with SEAMLESS cross-tile
// pipelining (ktiles%4==0 so the buffer ring continues across tiles; the
// tail kts of tile i prefetch stages 0..2 of tile i+1).
// Operand layout: within each 16-float K-group, logical k stored at phys
//   perm(r,k) = [4*(k&3) + (k>>2)] ^ ((r&2)?2:0)
// The base kperm16 makes each mma fragment a contiguous 8B pair; the row-
// dependent ^2 staggers 8B halves so rows 2 apart use disjoint banks ->
// all lds.64 fragment loads are conflict-free. Per-thread this reduces to
// kk_phys = kk ^ ((lg>>1)&1) since all fragment row bases are %8==0.
// All operands pre-rounded to tf32 with cvt.rna (kills truncation bias).
// ============================================================================

#define DINL __device__ __forceinline__

constexpr int BATCH = 4096, IN = 2048, HID = 4096, NCLS = 1000, NCLS_PAD = 1024;

constexpr int BM = 128, BN = 128, BK = 16;
constexpr int STAGES = 4;
constexpr int A_STAGE = BM * BK * 4;        // 8192 B
constexpr int B_STAGE = BN * BK * 4;        // 8192 B
constexpr int B_OFF = STAGES * A_STAGE;     // 32768
constexpr int SMEM_TOT = STAGES * (A_STAGE + B_STAGE);   // 65536 B

constexpr int MF = 4, NF = 4;               // warp tile 64 x 32
constexpr int NSM = 152;                    // GB300 SMs
constexpr int GRID = 2 * NSM;               // 2 CTAs/SM persistent

// device scratch (allocation-guard-safe)
__device__ float g_h1 [(size_t)BATCH * HID];
__device__ float g_h2 [(size_t)BATCH * HID];
__device__ float g_xr [(size_t)BATCH * IN];
__device__ float g_w1t[(size_t)HID * IN];
__device__ float g_w2t[(size_t)HID * HID];
__device__ float g_w3t[(size_t)NCLS_PAD * HID];

// ---------------------------------------------------------------- helpers
DINL uint32_t s2u(const void* p) {
    uint32_t a;
    asm("{ .reg .u64 t; cvta.to.shared.u64 t, %1; cvt.u32.u64 %0, t; }"
        : "=r"(a) : "l"(p));
    return a;
}
DINL void cp_async16(uint32_t s, const void* g) {
    asm volatile("cp.async.cg.shared.global [%0], [%1], 16;" :: "r"(s), "l"(g));
}
DINL void cp_commit() { asm volatile("cp.async.commit_group;" ::: "memory"); }
#define CP_WAIT(n) asm volatile("cp.async.wait_group %0;" :: "n"(n) : "memory")

DINL uint2 lds64(uint32_t a) {
    uint2 v;
    asm volatile("ld.shared.v2.b32 {%0,%1}, [%2];"
                 : "=r"(v.x), "=r"(v.y) : "r"(a));
    return v;
}
DINL float rna_tf32(float x) {
    uint32_t o;
    asm("cvt.rna.tf32.f32 %0, %1;" : "=r"(o) : "f"(x));
    return __uint_as_float(o);
}
DINL void mma1688(float* d, uint32_t a0, uint32_t a1, uint32_t a2, uint32_t a3,
                  uint32_t b0, uint32_t b1) {
    asm volatile(
        "mma.sync.aligned.m16n8k8.row.col.f32.tf32.tf32.f32 "
        "{%0,%1,%2,%3}, {%4,%5,%6,%7}, {%8,%9}, {%0,%1,%2,%3};"
        : "+f"(d[0]), "+f"(d[1]), "+f"(d[2]), "+f"(d[3])
        : "r"(a0), "r"(a1), "r"(a2), "r"(a3), "r"(b0), "r"(b1));
}
// base permutation: logical j (0..15) -> phys 4*(j&3) + (j>>2)
DINL int kperm16(int j) { return 4 * (j & 3) + ((j >> 2) & 3); }

// ------------------------------------------------------------------ GEMM
// A [M,K] row-major (tf32-rounded, row-swizzled 16-perm), Bt [Npad,K] same,
// C [M,N].  flags: bit0 relu, bit1 rna output, bit2 perm+swizzle output.
__global__ __launch_bounds__(256, 2)
void mlp_gemm_mma(const float* __restrict__ A, const float* __restrict__ Bt,
                  const float* __restrict__ bias, float* __restrict__ C,
                  int K, int N, int Mt, int Nt, int flags) {
    extern __shared__ char smem[];
    const uint32_t sb = s2u(smem);
    const int tid = threadIdx.x;
    const int wid = tid >> 5, lid = tid & 31;
    const int warp_m = wid & 1;           // 0..1  (64 rows each)
    const int warp_n = wid >> 1;          // 0..3  (32 cols each)
    const int lg = lid >> 2;              // 0..7
    const int lc = lid & 3;               // 0..3
    const uint32_t swz8 = 8u * ((lg >> 1) & 1);   // 8B row-swizzle term
    const int ktiles = K / BK;
    const int ntile = Mt * Nt;
    const int do_relu = flags & 1, do_rna = flags & 2, do_perm = flags & 4;

    int idx = blockIdx.x;
    if (idx >= ntile) return;

    // per-thread cp.async targets: A 512 chunks (2/thread), B 512 (2/thread)
    const int ld_row = tid >> 2, ld_j = tid & 3;     // rows 0..63 (+64)

    auto load_stage = [&](const float* Ag, const float* Bg, int kt, int buf) {
        const float* ap = Ag + kt * BK;
        const uint32_t ab = sb + buf * A_STAGE;
#pragma unroll
        for (int t = 0; t < 2; t++) {
            int row = ld_row + t * 64;
            cp_async16(ab + row * 64 + ld_j * 16, ap + (size_t)row * K + ld_j * 4);
        }
        const float* bp = Bg + kt * BK;
        const uint32_t bb = sb + B_OFF + buf * B_STAGE;
#pragma unroll
        for (int t = 0; t < 2; t++) {
            int row = ld_row + t * 64;
            cp_async16(bb + row * 64 + ld_j * 16, bp + (size_t)row * K + ld_j * 4);
        }
    };

    int m0 = (idx % Mt) * BM, n0 = (idx / Mt) * BN;
    const float* Ag = A + (size_t)m0 * K;
    const float* Bg = Bt + (size_t)n0 * K;

    // prologue: stages 0..2 of the first tile
    for (int s = 0; s < STAGES - 1; s++) { load_stage(Ag, Bg, s, s); cp_commit(); }

    // fragment base byte addrs (buffer 0)
    const uint32_t a_t0 = sb + (warp_m * 64 + lg) * 64 + 16 * lc;
    const uint32_t b_t0 = sb + B_OFF + (warp_n * 32 + lg) * 64 + 16 * lc;

    for (;;) {
        const int nidx = idx + GRID;
        const int valid = nidx < ntile;
        const float* Agn = valid ? A + (size_t)((nidx % Mt) * BM) * K : Ag;
        const float* Bgn = valid ? Bt + (size_t)((nidx / Mt) * BN) * K : Bg;

        float acc[MF][NF][4];
#pragma unroll
        for (int i = 0; i < MF; i++)
#pragma unroll
            for (int j = 0; j < NF; j++)
#pragma unroll
                for (int r = 0; r < 4; r++) acc[i][j][r] = 0.f;

        for (int kt = 0; kt < ktiles; kt++) {
            const int b = kt & (STAGES - 1);
            CP_WAIT(STAGES - 2);
            __syncthreads();

            const int nk = kt + STAGES - 1;
            if (nk < ktiles)      load_stage(Ag, Bg, nk, nk & (STAGES - 1));
            else if (valid)       load_stage(Agn, Bgn, nk - ktiles, nk & (STAGES - 1));
            cp_commit();

            const uint32_t ab = a_t0 + b * A_STAGE;
            const uint32_t bb = b_t0 + b * B_STAGE;
#pragma unroll
            for (int kk = 0; kk < 2; kk++) {
                const uint32_t ko = (8u * kk) ^ swz8;
                uint2 af[MF][2];
#pragma unroll
                for (int mf = 0; mf < MF; mf++) {
                    af[mf][0] = lds64(ab + mf * 1024 + ko);        // row lg
                    af[mf][1] = lds64(ab + mf * 1024 + 512 + ko);  // row lg+8
                }
                uint2 bf[NF];
#pragma unroll
                for (int nf = 0; nf < NF; nf++)
                    bf[nf] = lds64(bb + nf * 512 + ko);
#pragma unroll
                for (int mf = 0; mf < MF; mf++)
#pragma unroll
                    for (int nf = 0; nf < NF; nf++)
                        mma1688(acc[mf][nf], af[mf][0].x, af[mf][1].x,
                                af[mf][0].y, af[mf][1].y, bf[nf].x, bf[nf].y);
            }
        }

        // ---- epilogue (next tile's stages already streaming in)
        float bvv[NF][2];
#pragma unroll
        for (int nf = 0; nf < NF; nf++) {
            const int c = n0 + warp_n * 32 + nf * 8 + 2 * lc;
            bvv[nf][0] = (c < N) ? __ldg(bias + c) : 0.f;
            bvv[nf][1] = (c + 1 < N) ? __ldg(bias + c + 1) : 0.f;
        }
#pragma unroll
        for (int mf = 0; mf < MF; mf++) {
#pragma unroll
            for (int r2 = 0; r2 < 2; r2++) {
                const int m = m0 + warp_m * 64 + mf * 16 + lg + r2 * 8;
                float* crow = C + (size_t)m * N;
                const int msw = (m & 2) ? 2 : 0;
#pragma unroll
                for (int nf = 0; nf < NF; nf++) {
                    const int c = n0 + warp_n * 32 + nf * 8 + 2 * lc;
                    float v0 = acc[mf][nf][r2 * 2 + 0] + bvv[nf][0];
                    float v1 = acc[mf][nf][r2 * 2 + 1] + bvv[nf][1];
                    if (do_relu) { v0 = fmaxf(v0, 0.f); v1 = fmaxf(v1, 0.f); }
                    if (do_rna)  { v0 = rna_tf32(v0);  v1 = rna_tf32(v1); }
                    if (do_perm) {
                        const int g = c & ~15;
                        crow[g + (kperm16(c & 15) ^ msw)]       = v0;
                        crow[g + (kperm16((c + 1) & 15) ^ msw)] = v1;
                    } else if (c < N) {
                        *(float2*)(crow + c) = make_float2(v0, v1);
                    }
                }
            }
        }

        if (!valid) break;
        idx = nidx;
        m0 = (idx % Mt) * BM; n0 = (idx / Mt) * BN;
        Ag = Agn; Bg = Bgn;
    }
}

// ---------------------------------------------------- fused prep (1 launch)
__device__ void transpose_job(const float* __restrict__ s, float* __restrict__ d,
                              int R, int C, int bx, int by) {
    __shared__ float t[32][33];
    const int tid = threadIdx.x;
    const int x = tid & 31, y = tid >> 5;   // 32 x 8
    const int c0 = bx * 32, r0 = by * 32;
#pragma unroll
    for (int i = y; i < 32; i += 8) {
        int r = r0 + i, c = c0 + x;
        t[i][x] = (c < C) ? s[(size_t)r * C + c] : 0.f;
    }
    __syncthreads();
#pragma unroll
    for (int i = y; i < 32; i += 8) {
        int cc = c0 + i, rr = r0 + x;         // cc = output row (N), rr = K pos
        int msw = (cc & 2) ? 2 : 0;
        int rp = (rr & ~15) | (kperm16(rr & 15) ^ msw);
        d[(size_t)cc * R + rp] = rna_tf32(t[x][i]);
    }
}

constexpr int G_W1 = (HID / 32) * (IN / 32);        // 8192
constexpr int G_W2 = (HID / 32) * (HID / 32);       // 16384
constexpr int G_W3 = (NCLS_PAD / 32) * (HID / 32);  // 4096
constexpr int G_X  = (BATCH * IN) / 4096;           // 2048
constexpr int G_PREP = G_W1 + G_W2 + G_W3 + G_X;

__global__ __launch_bounds__(256)
void prep_all(const float* __restrict__ w1, const float* __restrict__ w2,
              const float* __restrict__ w3, const float* __restrict__ x,
              float* __restrict__ w1t, float* __restrict__ w2t,
              float* __restrict__ w3t, float* __restrict__ xr) {
    int id = blockIdx.x;
    if (id < G_W1) {
        transpose_job(w1, w1t, IN, HID, id % (HID / 32), id / (HID / 32));
        return;
    }
    id -= G_W1;
    if (id < G_W2) {
        transpose_job(w2, w2t, HID, HID, id % (HID / 32), id / (HID / 32));
        return;
    }
    id -= G_W2;
    if (id < G_W3) {
        transpose_job(w3, w3t, HID, NCLS, id % (NCLS_PAD / 32), id / (NCLS_PAD / 32));
        return;
    }
    id -= G_W3;
    // x: rna + row-swizzled 16-perm; 16 floats/thread (a 4x4 transpose of
    // four float4s, with 8B-half swap on rows where bit1 is set).
    const size_t base = (size_t)id * 4096 + threadIdx.x * 16;
    const int row = (int)(base >> 11);              // 2048 floats per row
    float4 i0 = *(const float4*)(x + base);
    float4 i1 = *(const float4*)(x + base + 4);
    float4 i2 = *(const float4*)(x + base + 8);
    float4 i3 = *(const float4*)(x + base + 12);
    float4 o0, o1, o2, o3;
    if (row & 2) {
        o0 = make_float4(rna_tf32(i2.x), rna_tf32(i3.x), rna_tf32(i0.x), rna_tf32(i1.x));
        o1 = make_float4(rna_tf32(i2.y), rna_tf32(i3.y), rna_tf32(i0.y), rna_tf32(i1.y));
        o2 = make_float4(rna_tf32(i2.z), rna_tf32(i3.z), rna_tf32(i0.z), rna_tf32(i1.z));
        o3 = make_float4(rna_tf32(i2.w), rna_tf32(i3.w), rna_tf32(i0.w), rna_tf32(i1.w));
    } else {
        o0 = make_float4(rna_tf32(i0.x), rna_tf32(i1.x), rna_tf32(i2.x), rna_tf32(i3.x));
        o1 = make_float4(rna_tf32(i0.y), rna_tf32(i1.y), rna_tf32(i2.y), rna_tf32(i3.y));
        o2 = make_float4(rna_tf32(i0.z), rna_tf32(i1.z), rna_tf32(i2.z), rna_tf32(i3.z));
        o3 = make_float4(rna_tf32(i0.w), rna_tf32(i1.w), rna_tf32(i2.w), rna_tf32(i3.w));
    }
    *(float4*)(xr + base)      = o0;
    *(float4*)(xr + base + 4)  = o1;
    *(float4*)(xr + base + 8)  = o2;
    *(float4*)(xr + base + 12) = o3;
}

// ----------------------------------------------------------------- launcher
extern "C" void kernel_launch(void* const* d_in, const int* in_sizes, int n_in,
                              void* d_out, int out_size) {
    (void)in_sizes; (void)n_in; (void)out_size;
    const float* x  = (const float*)d_in[0];
    const float* w1 = (const float*)d_in[1];
    const float* b1 = (const float*)d_in[2];
    const float* w2 = (const float*)d_in[3];
    const float* b2 = (const float*)d_in[4];
    const float* w3 = (const float*)d_in[5];
    const float* b3 = (const float*)d_in[6];
    float* out = (float*)d_out;

    float *h1, *h2, *xr, *w1t, *w2t, *w3t;
    cudaGetSymbolAddress((void**)&h1,  g_h1);
    cudaGetSymbolAddress((void**)&h2,  g_h2);
    cudaGetSymbolAddress((void**)&xr,  g_xr);
    cudaGetSymbolAddress((void**)&w1t, g_w1t);
    cudaGetSymbolAddress((void**)&w2t, g_w2t);
    cudaGetSymbolAddress((void**)&w3t, g_w3t);

    cudaFuncSetAttribute(mlp_gemm_mma,
                         cudaFuncAttributeMaxDynamicSharedMemorySize, SMEM_TOT);

    prep_all<<<G_PREP, 256>>>(w1, w2, w3, x, w1t, w2t, w3t, xr);

    const int MT = BATCH / BM;                 // 32
    mlp_gemm_mma<<<GRID, 256, SMEM_TOT>>>(
        xr, w1t, b1, h1, IN, HID, MT, HID / BN, /*relu|rna|perm*/ 7);
    mlp_gemm_mma<<<GRID, 256, SMEM_TOT>>>(
        h1, w2t, b2, h2, HID, HID, MT, HID / BN, 7);
    mlp_gemm_mma<<<GRID, 256, SMEM_TOT>>>(
        h2, w3t, b3, out, HID, NCLS, MT, NCLS_PAD / BN, 0);
}

// round 9
// speedup vs baseline: 2.6126x; 1.3950x over previous
#include <cuda_runtime.h>
#include <cuda_fp16.h>
#include <cstdint>

// ============================================================================
// 3-layer MLP via mma.sync.m16n8k16.f32.f16.f16.f32 on sm_103a.
//   out = relu(relu(x@w1+b1)@w2+b2)@w3+b3
// fp16 operands (same 11-bit mantissa as tf32 -> same error class) at the
// full-rate HMMA pipe; f32 accumulate. CTA 128x256, 512 threads, 16 warps
// (2Mx8N grid, warp tile 64x32), BK=16, 8-stage cp.async ring, persistent
// CTAs with seamless cross-tile pipelining (ktiles%8==0).
// Operand layout: within each 16-element K-group, logical k stored at
//   hperm(k) = 4*((k>>1)&3) + 2*(k>>3) + (k&1)
// so each mma fragment (a0,a2 / a1,a3 / b0,b1) is ONE conflict-free lds.64
// (rows are 32B; each 16-lane phase covers one 128B stretch exactly).
// h1/h2 live as permuted fp16 in gmem (halves DRAM traffic as well).
// ============================================================================

#define DINL __device__ __forceinline__

constexpr int BATCH = 4096, IN = 2048, HID = 4096, NCLS = 1000, NCLS_PAD = 1024;

constexpr int BM = 128, BN = 256, BK = 16;
constexpr int STAGES = 8;
constexpr int A_ST = BM * BK * 2;           // 4096 B
constexpr int B_ST = BN * BK * 2;           // 8192 B
constexpr int B_OFF = STAGES * A_ST;        // 32768
constexpr int SMEM_TOT = STAGES * (A_ST + B_ST);   // 98304 B

constexpr int MF = 4, NF = 4;               // warp tile 64 x 32
constexpr int NSM = 152;
constexpr int GRID = NSM;                   // 1 CTA/SM persistent (512 thr)

// device scratch (allocation-guard-safe), all fp16 permuted layouts
__device__ __half g_h1 [(size_t)BATCH * HID];
__device__ __half g_h2 [(size_t)BATCH * HID];
__device__ __half g_xr [(size_t)BATCH * IN];
__device__ __half g_w1t[(size_t)HID * IN];
__device__ __half g_w2t[(size_t)HID * HID];
__device__ __half g_w3t[(size_t)NCLS_PAD * HID];

// ---------------------------------------------------------------- helpers
DINL uint32_t s2u(const void* p) {
    uint32_t a;
    asm("{ .reg .u64 t; cvta.to.shared.u64 t, %1; cvt.u32.u64 %0, t; }"
        : "=r"(a) : "l"(p));
    return a;
}
DINL void cp_async16(uint32_t s, const void* g) {
    asm volatile("cp.async.cg.shared.global [%0], [%1], 16;" :: "r"(s), "l"(g));
}
DINL void cp_commit() { asm volatile("cp.async.commit_group;" ::: "memory"); }
#define CP_WAIT(n) asm volatile("cp.async.wait_group %0;" :: "n"(n) : "memory")

DINL uint2 lds64(uint32_t a) {
    uint2 v;
    asm volatile("ld.shared.v2.b32 {%0,%1}, [%2];"
                 : "=r"(v.x), "=r"(v.y) : "r"(a));
    return v;
}
DINL void mma16816(float* d, uint32_t a0, uint32_t a1, uint32_t a2, uint32_t a3,
                   uint32_t b0, uint32_t b1) {
    asm volatile(
        "mma.sync.aligned.m16n8k16.row.col.f32.f16.f16.f32 "
        "{%0,%1,%2,%3}, {%4,%5,%6,%7}, {%8,%9}, {%0,%1,%2,%3};"
        : "+f"(d[0]), "+f"(d[1]), "+f"(d[2]), "+f"(d[3])
        : "r"(a0), "r"(a1), "r"(a2), "r"(a3), "r"(b0), "r"(b1));
}
// fp16 K-permutation: logical j (0..15) -> phys 4*((j>>1)&3) + 2*(j>>3) + (j&1)
DINL int hperm16(int j) { return 4 * ((j >> 1) & 3) + 2 * ((j >> 3) & 1) + (j & 1); }

// ------------------------------------------------------------------ GEMM
// A [M,K] fp16 row-major (hperm16 within 16-groups), Bt [Npad,K] fp16 same,
// Cv: fp16 (permuted, layers 1/2) or f32 plain (layer 3).
// flags: bit0 relu, bit1 fp16-permuted output (else f32 plain).
__global__ __launch_bounds__(512, 1)
void mlp_gemm_h(const __half* __restrict__ A, const __half* __restrict__ Bt,
                const float* __restrict__ bias, void* __restrict__ Cv,
                int K, int N, int Mt, int Nt, int flags) {
    extern __shared__ char smem[];
    const uint32_t sb = s2u(smem);
    const int tid = threadIdx.x;
    const int wid = tid >> 5, lid = tid & 31;
    const int warp_m = wid & 1;           // 0..1  (64 rows)
    const int warp_n = wid >> 1;          // 0..7  (32 cols)
    const int lg = lid >> 2;              // 0..7
    const int lc = lid & 3;               // 0..3
    const int ktiles = K / BK;
    const int ntile = Mt * Nt;
    const int do_relu = flags & 1, do_h16 = flags & 2;

    int idx = blockIdx.x;
    if (idx >= ntile) return;

    auto load_stage = [&](const __half* Ag, const __half* Bg, int kt, int buf) {
        const __half* bp = Bg + kt * BK;
        const uint32_t bb = sb + B_OFF + buf * B_ST;
        {
            const int row = tid >> 1, j = tid & 1;      // 256 rows x 2
            cp_async16(bb + row * 32 + j * 16, bp + (size_t)row * K + j * 8);
        }
        if (tid < 256) {
            const __half* ap = Ag + kt * BK;
            const uint32_t ab = sb + buf * A_ST;
            const int row = tid >> 1, j = tid & 1;      // 128 rows x 2
            cp_async16(ab + row * 32 + j * 16, ap + (size_t)row * K + j * 8);
        }
    };

    int m0 = (idx % Mt) * BM, n0 = (idx / Mt) * BN;
    const __half* Ag = A + (size_t)m0 * K;
    const __half* Bg = Bt + (size_t)n0 * K;

    for (int s = 0; s < STAGES - 1; s++) { load_stage(Ag, Bg, s, s); cp_commit(); }

    // fragment base byte addrs (buffer 0); rows are 32B
    const uint32_t a_t0 = sb + (warp_m * 64 + lg) * 32 + 8 * lc;
    const uint32_t b_t0 = sb + B_OFF + (warp_n * 32 + lg) * 32 + 8 * lc;

    for (;;) {
        const int nidx = idx + GRID;
        const int valid = nidx < ntile;
        const __half* Agn = valid ? A + (size_t)((nidx % Mt) * BM) * K : Ag;
        const __half* Bgn = valid ? Bt + (size_t)((nidx / Mt) * BN) * K : Bg;

        float acc[MF][NF][4];
#pragma unroll
        for (int i = 0; i < MF; i++)
#pragma unroll
            for (int j = 0; j < NF; j++)
#pragma unroll
                for (int r = 0; r < 4; r++) acc[i][j][r] = 0.f;

        for (int kt = 0; kt < ktiles; kt++) {
            const int b = kt & (STAGES - 1);
            CP_WAIT(STAGES - 2);
            __syncthreads();

            const int nk = kt + STAGES - 1;
            if (nk < ktiles)  load_stage(Ag, Bg, nk, nk & (STAGES - 1));
            else if (valid)   load_stage(Agn, Bgn, nk - ktiles, nk & (STAGES - 1));
            cp_commit();

            const uint32_t ab = a_t0 + b * A_ST;
            const uint32_t bb = b_t0 + b * B_ST;

            uint2 af[MF][2];
#pragma unroll
            for (int mf = 0; mf < MF; mf++) {
                af[mf][0] = lds64(ab + mf * 512);        // row lg   -> a0,a2
                af[mf][1] = lds64(ab + mf * 512 + 256);  // row lg+8 -> a1,a3
            }
            uint2 bf[NF];
#pragma unroll
            for (int nf = 0; nf < NF; nf++)
                bf[nf] = lds64(bb + nf * 256);           // col lg   -> b0,b1
#pragma unroll
            for (int mf = 0; mf < MF; mf++)
#pragma unroll
                for (int nf = 0; nf < NF; nf++)
                    mma16816(acc[mf][nf], af[mf][0].x, af[mf][1].x,
                             af[mf][0].y, af[mf][1].y, bf[nf].x, bf[nf].y);
        }

        // ---- epilogue (next tile's stages already streaming)
        float bvv[NF][2];
#pragma unroll
        for (int nf = 0; nf < NF; nf++) {
            const int c = n0 + warp_n * 32 + nf * 8 + 2 * lc;
            bvv[nf][0] = (c < N) ? __ldg(bias + c) : 0.f;
            bvv[nf][1] = (c + 1 < N) ? __ldg(bias + c + 1) : 0.f;
        }
#pragma unroll
        for (int mf = 0; mf < MF; mf++) {
#pragma unroll
            for (int r2 = 0; r2 < 2; r2++) {
                const int m = m0 + warp_m * 64 + mf * 16 + lg + r2 * 8;
#pragma unroll
                for (int nf = 0; nf < NF; nf++) {
                    const int c = n0 + warp_n * 32 + nf * 8 + 2 * lc;
                    float v0 = acc[mf][nf][r2 * 2 + 0] + bvv[nf][0];
                    float v1 = acc[mf][nf][r2 * 2 + 1] + bvv[nf][1];
                    if (do_relu) { v0 = fmaxf(v0, 0.f); v1 = fmaxf(v1, 0.f); }
                    if (do_h16) {
                        __half* crow = (__half*)Cv + (size_t)m * N;
                        const int pidx = (c & ~15) + 4 * lc + 2 * (nf & 1);
                        *(__half2*)(crow + pidx) = __floats2half2_rn(v0, v1);
                    } else if (c < N) {
                        float* crow = (float*)Cv + (size_t)m * N;
                        *(float2*)(crow + c) = make_float2(v0, v1);
                    }
                }
            }
        }

        if (!valid) break;
        idx = nidx;
        m0 = (idx % Mt) * BM; n0 = (idx / Mt) * BN;
        Ag = Agn; Bg = Bgn;
    }
}

// ---------------------------------------------------- fused prep (1 launch)
__device__ void transpose_job(const float* __restrict__ s, __half* __restrict__ d,
                              int R, int C, int bx, int by) {
    __shared__ float t[32][33];
    const int tid = threadIdx.x;
    const int x = tid & 31, y = tid >> 5;   // 32 x 8
    const int c0 = bx * 32, r0 = by * 32;
#pragma unroll
    for (int i = y; i < 32; i += 8) {
        int r = r0 + i, c = c0 + x;
        t[i][x] = (c < C) ? s[(size_t)r * C + c] : 0.f;
    }
    __syncthreads();
#pragma unroll
    for (int i = y; i < 32; i += 8) {
        int cc = c0 + i, rr = r0 + x;        // cc = out row (N), rr = K pos
        int rp = (rr & ~15) | hperm16(rr & 15);
        d[(size_t)cc * R + rp] = __float2half_rn(t[x][i]);
    }
}

constexpr int G_W1 = (HID / 32) * (IN / 32);        // 8192
constexpr int G_W2 = (HID / 32) * (HID / 32);       // 16384
constexpr int G_W3 = (NCLS_PAD / 32) * (HID / 32);  // 4096
constexpr int G_X  = (BATCH * IN) / 4096;           // 2048
constexpr int G_PREP = G_W1 + G_W2 + G_W3 + G_X;

__global__ __launch_bounds__(256)
void prep_all(const float* __restrict__ w1, const float* __restrict__ w2,
              const float* __restrict__ w3, const float* __restrict__ x,
              __half* __restrict__ w1t, __half* __restrict__ w2t,
              __half* __restrict__ w3t, __half* __restrict__ xr) {
    int id = blockIdx.x;
    if (id < G_W1) {
        transpose_job(w1, w1t, IN, HID, id % (HID / 32), id / (HID / 32));
        return;
    }
    id -= G_W1;
    if (id < G_W2) {
        transpose_job(w2, w2t, HID, HID, id % (HID / 32), id / (HID / 32));
        return;
    }
    id -= G_W2;
    if (id < G_W3) {
        transpose_job(w3, w3t, HID, NCLS, id % (NCLS_PAD / 32), id / (NCLS_PAD / 32));
        return;
    }
    id -= G_W3;
    // x: fp16-convert + hperm16; 16 floats/thread (one K-group)
    const size_t base = (size_t)id * 4096 + threadIdx.x * 16;
    float f[16];
#pragma unroll
    for (int i = 0; i < 16; i += 4) *(float4*)&f[i] = *(const float4*)(x + base + i);
    __half2 o[8];
#pragma unroll
    for (int j = 0; j < 8; j++) {
        const int l = 8 * (j & 1) + 2 * (j >> 1);   // phys pair (2j,2j+1) <- logical (l,l+1)
        o[j] = __floats2half2_rn(f[l], f[l + 1]);
    }
    *(uint4*)(xr + base)     = *(uint4*)&o[0];
    *(uint4*)(xr + base + 8) = *(uint4*)&o[4];
}

// ----------------------------------------------------------------- launcher
extern "C" void kernel_launch(void* const* d_in, const int* in_sizes, int n_in,
                              void* d_out, int out_size) {
    (void)in_sizes; (void)n_in; (void)out_size;
    const float* x  = (const float*)d_in[0];
    const float* w1 = (const float*)d_in[1];
    const float* b1 = (const float*)d_in[2];
    const float* w2 = (const float*)d_in[3];
    const float* b2 = (const float*)d_in[4];
    const float* w3 = (const float*)d_in[5];
    const float* b3 = (const float*)d_in[6];

    __half *h1, *h2, *xr, *w1t, *w2t, *w3t;
    cudaGetSymbolAddress((void**)&h1,  g_h1);
    cudaGetSymbolAddress((void**)&h2,  g_h2);
    cudaGetSymbolAddress((void**)&xr,  g_xr);
    cudaGetSymbolAddress((void**)&w1t, g_w1t);
    cudaGetSymbolAddress((void**)&w2t, g_w2t);
    cudaGetSymbolAddress((void**)&w3t, g_w3t);

    cudaFuncSetAttribute(mlp_gemm_h,
                         cudaFuncAttributeMaxDynamicSharedMemorySize, SMEM_TOT);

    prep_all<<<G_PREP, 256>>>(w1, w2, w3, x, w1t, w2t, w3t, xr);

    const int MT = BATCH / BM;                 // 32
    mlp_gemm_h<<<GRID, 512, SMEM_TOT>>>(
        xr, w1t, b1, h1, IN, HID, MT, HID / BN, /*relu|h16*/ 3);
    mlp_gemm_h<<<GRID, 512, SMEM_TOT>>>(
        h1, w2t, b2, h2, HID, HID, MT, HID / BN, 3);
    mlp_gemm_h<<<GRID, 512, SMEM_TOT>>>(
        h2, w3t, b3, d_out, HID, NCLS, MT, NCLS_PAD / BN, 0);
}